// round 9
// baseline (speedup 1.0000x reference)
#include <cuda_runtime.h>

#define BATCH 8
#define N2 2048
#define KNN 40
#define NJ (N2*KNN)
#define KBN 0.9999950000374997f
#define NEGINF (-3.402823466e38f)
#define KSPLIT_XR 4

// ------------------------- device scratch (no allocation allowed) -------------------------
__device__ float g_dist[(size_t)BATCH*N2*N2];      // neg-dist / energy / attn (reused)
__device__ int   g_idx[BATCH*N2*KNN];
__device__ float g_bufF[(size_t)BATCH*6*NJ];       // stage-1 gathered features
__device__ float g_bufA[(size_t)BATCH*64*NJ];      // edge-conv ping / xr partials
__device__ float g_bufB[(size_t)BATCH*64*NJ];      // edge-conv pong
__device__ float g_h[BATCH*128*N2];                // [x1;x2] then SA running h (b,c,n)
__device__ float g_x1t[BATCH*N2*64];               // x1 point-major for gathers
__device__ float g_xx[BATCH*N2];
__device__ float g_q[BATCH*32*N2];
__device__ float g_v[BATCH*128*N2];
__device__ float g_dd[BATCH*128*N2];               // d = h - xr
__device__ float g_cs[BATCH*N2];                   // 1/(1e-9+colsum)
__device__ float g_tbuf[BATCH*64*N2];              // hoisted center term
__device__ float g_outs[(size_t)BATCH*512*N2];     // concat of 4 SA outputs
__device__ float g_w3d[64*64];                     // w3b - w3a

enum { EP_NONE=0, EP_ND=1, EP_BN_LRELU=2, EP_BN_LRELU_T40=3, EP_VBIAS=4, EP_XR=5, EP_TRES=6 };

struct GemmP {
    const float* A; const float* B; float* C;
    int M, N, K;
    int a_rs, a_cs;          // A element (m,k) at A[m*a_rs + k*a_cs]
    int b_rs, b_cs;          // B element (k,n) at B[k*b_rs + n*b_cs]
    int ldc;
    long long aBS, bBS, cBS; // per-batch strides (0 = shared weights)
    int mode;
    int ksplit;              // split-K factor (grid.y = (M/BM)*ksplit)
    long long kPartStride;   // C offset per k-chunk
    const float* s; const float* bias; const float* bias2;
    const float* aux;  long long auxBS; int ldaux;   // tbuf / xx / recip
    const float* aux2; long long aux2BS;             // h (for EP_XR)
    float* aux3; long long aux3BS; int ldaux3;       // outs slice (EP_TRES)
};

// ============ fast SGEMM: BMx128 tiles, 8x8 micro, f32x2 FMA, A duplicated in smem ============
// Requirements (guaranteed by callers): K%(16*ksplit)==0, M%BM==0, N%128==0, b_cs==1,
// A either k-contiguous (a_cs==1) or m-contiguous (a_rs==1), 16B-aligned bases.
template<int BM, int MAXNCTA>
__global__ __launch_bounds__(BM*2, MAXNCTA) void sgemm2_kernel(GemmP p) {
    constexpr int THREADS = BM * 2;
    constexpr int NB4 = 512 / THREADS;       // B float4 slots per thread
    constexpr int LDA = 2 * BM;              // duplicated A row (floats)
    __shared__ __align__(16) float As[2][16][LDA];   // element m stored at [2m],[2m+1]
    __shared__ __align__(16) float Bs[2][16][128];

    int b = blockIdx.z;
    const float* A = p.A + (size_t)b * p.aBS;
    const float* B = p.B + (size_t)b * p.bBS;
    int ks   = blockIdx.y % p.ksplit;
    int rowb = blockIdx.y / p.ksplit;
    float* C = p.C + (size_t)b * p.cBS + (size_t)ks * p.kPartStride;
    int kBase = ks * (p.K / p.ksplit);
    int row0 = rowb * BM, col0 = blockIdx.x * 128;
    int tid = threadIdx.x;
    int tx = tid & 15, ty = tid >> 4;

    unsigned long long acc[8][4];
    #pragma unroll
    for (int i = 0; i < 8; i++)
        #pragma unroll
        for (int j = 0; j < 4; j++) acc[i][j] = 0ull;

    float4 ra[2];
    float4 rb[NB4];
    const int T = (p.K / p.ksplit) >> 4;
    const bool akc = (p.a_cs == 1);

    // ---- tile 0 global->reg ----
    {
        if (akc) {
            #pragma unroll
            for (int i = 0; i < 2; i++) {
                int s = tid + i * THREADS;
                int m = s >> 2, k4 = (s & 3) << 2;
                ra[i] = *(const float4*)&A[(size_t)(row0 + m) * p.a_rs + kBase + k4];
            }
        } else {
            #pragma unroll
            for (int i = 0; i < 2; i++) {
                int s = tid + i * THREADS;
                int m4 = s % (BM / 4), k = s / (BM / 4);
                ra[i] = *(const float4*)&A[(size_t)(kBase + k) * p.a_cs + row0 + m4 * 4];
            }
        }
        #pragma unroll
        for (int i = 0; i < NB4; i++) {
            int s = tid + i * THREADS;
            int k = s >> 5, n4 = (s & 31) << 2;
            rb[i] = *(const float4*)&B[(size_t)(kBase + k) * p.b_rs + col0 + n4];
        }
    }
    // ---- reg->smem buf 0 (A duplicated) ----
    {
        if (akc) {
            #pragma unroll
            for (int i = 0; i < 2; i++) {
                int s = tid + i * THREADS;
                int m = s >> 2, k4 = (s & 3) << 2;
                float v[4] = {ra[i].x, ra[i].y, ra[i].z, ra[i].w};
                #pragma unroll
                for (int d = 0; d < 4; d++)
                    *(float2*)&As[0][k4 + d][2 * m] = make_float2(v[d], v[d]);
            }
        } else {
            #pragma unroll
            for (int i = 0; i < 2; i++) {
                int s = tid + i * THREADS;
                int m4 = s % (BM / 4), k = s / (BM / 4);
                float4 lo = make_float4(ra[i].x, ra[i].x, ra[i].y, ra[i].y);
                float4 hi = make_float4(ra[i].z, ra[i].z, ra[i].w, ra[i].w);
                *(float4*)&As[0][k][8 * m4]     = lo;
                *(float4*)&As[0][k][8 * m4 + 4] = hi;
            }
        }
        #pragma unroll
        for (int i = 0; i < NB4; i++) {
            int s = tid + i * THREADS;
            int k = s >> 5, n4 = (s & 31) << 2;
            *(float4*)&Bs[0][k][n4] = rb[i];
        }
    }
    __syncthreads();

    int cur = 0;
    for (int t = 0; t < T; t++) {
        if (t + 1 < T) {
            int k0 = kBase + ((t + 1) << 4);
            if (akc) {
                #pragma unroll
                for (int i = 0; i < 2; i++) {
                    int s = tid + i * THREADS;
                    int m = s >> 2, k4 = (s & 3) << 2;
                    ra[i] = *(const float4*)&A[(size_t)(row0 + m) * p.a_rs + k0 + k4];
                }
            } else {
                #pragma unroll
                for (int i = 0; i < 2; i++) {
                    int s = tid + i * THREADS;
                    int m4 = s % (BM / 4), k = s / (BM / 4);
                    ra[i] = *(const float4*)&A[(size_t)(k0 + k) * p.a_cs + row0 + m4 * 4];
                }
            }
            #pragma unroll
            for (int i = 0; i < NB4; i++) {
                int s = tid + i * THREADS;
                int k = s >> 5, n4 = (s & 31) << 2;
                rb[i] = *(const float4*)&B[(size_t)(k0 + k) * p.b_rs + col0 + n4];
            }
        }
        #pragma unroll
        for (int k = 0; k < 16; k++) {
            const float* ap = &As[cur][k][ty * 16];
            ulonglong2 a01 = *(const ulonglong2*)(ap);
            ulonglong2 a23 = *(const ulonglong2*)(ap + 4);
            ulonglong2 a45 = *(const ulonglong2*)(ap + 8);
            ulonglong2 a67 = *(const ulonglong2*)(ap + 12);
            unsigned long long ad[8] = {a01.x, a01.y, a23.x, a23.y,
                                        a45.x, a45.y, a67.x, a67.y};
            unsigned long long bp[4];
            {
                ulonglong2 q0 = *(const ulonglong2*)&Bs[cur][k][tx * 4];
                ulonglong2 q1 = *(const ulonglong2*)&Bs[cur][k][64 + tx * 4];
                bp[0] = q0.x; bp[1] = q0.y; bp[2] = q1.x; bp[3] = q1.y;
            }
            #pragma unroll
            for (int i = 0; i < 8; i++)
                #pragma unroll
                for (int j = 0; j < 4; j++)
                    asm("fma.rn.f32x2 %0, %1, %2, %0;"
                        : "+l"(acc[i][j]) : "l"(ad[i]), "l"(bp[j]));
        }
        if (t + 1 < T) {
            int nb = cur ^ 1;
            if (akc) {
                #pragma unroll
                for (int i = 0; i < 2; i++) {
                    int s = tid + i * THREADS;
                    int m = s >> 2, k4 = (s & 3) << 2;
                    float v[4] = {ra[i].x, ra[i].y, ra[i].z, ra[i].w};
                    #pragma unroll
                    for (int d = 0; d < 4; d++)
                        *(float2*)&As[nb][k4 + d][2 * m] = make_float2(v[d], v[d]);
                }
            } else {
                #pragma unroll
                for (int i = 0; i < 2; i++) {
                    int s = tid + i * THREADS;
                    int m4 = s % (BM / 4), k = s / (BM / 4);
                    float4 lo = make_float4(ra[i].x, ra[i].x, ra[i].y, ra[i].y);
                    float4 hi = make_float4(ra[i].z, ra[i].z, ra[i].w, ra[i].w);
                    *(float4*)&As[nb][k][8 * m4]     = lo;
                    *(float4*)&As[nb][k][8 * m4 + 4] = hi;
                }
            }
            #pragma unroll
            for (int i = 0; i < NB4; i++) {
                int s = tid + i * THREADS;
                int k = s >> 5, n4 = (s & 31) << 2;
                *(float4*)&Bs[nb][k][n4] = rb[i];
            }
            __syncthreads();
            cur = nb;
        }
    }

    // ---- epilogue: cols col0+tx*4+{0..3} and col0+64+tx*4+{0..3} ----
    #pragma unroll
    for (int i = 0; i < 8; i++) {
        int r = row0 + ty * 8 + i;
        float vals[8];
        #pragma unroll
        for (int j = 0; j < 4; j++) {
            float lo, hi;
            asm("mov.b64 {%0, %1}, %2;" : "=f"(lo), "=f"(hi) : "l"(acc[i][j]));
            vals[2 * j] = lo; vals[2 * j + 1] = hi;
        }
        #pragma unroll
        for (int g = 0; g < 2; g++) {
            int c0 = col0 + g * 64 + tx * 4;
            size_t pos = (size_t)r * p.ldc + c0;
            float4 w;
            float* wf = (float*)&w;
            switch (p.mode) {
                case EP_NONE: {
                    #pragma unroll
                    for (int j = 0; j < 4; j++) wf[j] = vals[g * 4 + j];
                } break;
                case EP_ND: {
                    const float* xx = p.aux + (size_t)b * p.auxBS;
                    float xr = xx[r];
                    float4 xc = *(const float4*)&xx[c0];
                    const float* xcf = (const float*)&xc;
                    #pragma unroll
                    for (int j = 0; j < 4; j++)
                        wf[j] = 2.f * vals[g * 4 + j] - xr - xcf[j];
                } break;
                case EP_BN_LRELU: {
                    float sc = p.s[r] * KBN, bi = p.bias[r];
                    #pragma unroll
                    for (int j = 0; j < 4; j++) {
                        float y = vals[g * 4 + j] * sc + bi;
                        wf[j] = y > 0.f ? y : 0.2f * y;
                    }
                } break;
                case EP_BN_LRELU_T40: {
                    const float* tt = p.aux + (size_t)b * p.auxBS + (size_t)r * p.ldaux;
                    float sc = p.s[r] * KBN, bi = p.bias[r];
                    #pragma unroll
                    for (int j = 0; j < 4; j++) {
                        float y = (vals[g * 4 + j] + tt[(c0 + j) / KNN]) * sc + bi;
                        wf[j] = y > 0.f ? y : 0.2f * y;
                    }
                } break;
                case EP_VBIAS: {
                    float bi = p.bias[r];
                    #pragma unroll
                    for (int j = 0; j < 4; j++) wf[j] = vals[g * 4 + j] + bi;
                } break;
                case EP_XR: {
                    const float* hh = p.aux2 + (size_t)b * p.aux2BS;
                    const float* rc = p.aux  + (size_t)b * p.auxBS;
                    float4 h4 = *(const float4*)&hh[pos];
                    float4 r4 = *(const float4*)&rc[c0];
                    const float* hf = (const float*)&h4;
                    const float* rf = (const float*)&r4;
                    #pragma unroll
                    for (int j = 0; j < 4; j++)
                        wf[j] = hf[j] - vals[g * 4 + j] * rf[j];
                } break;
                case EP_TRES: {
                    float sc = p.s[r] * KBN;
                    float tb = p.bias[r], bb2 = p.bias2[r];
                    float4 o4 = *(const float4*)&C[pos];
                    const float* of = (const float*)&o4;
                    float* outp = p.aux3 + (size_t)b * p.aux3BS + (size_t)r * p.ldaux3 + c0;
                    float4 w2;
                    float* w2f = (float*)&w2;
                    #pragma unroll
                    for (int j = 0; j < 4; j++) {
                        float y = (vals[g * 4 + j] + tb) * sc + bb2;
                        y = y > 0.f ? y : 0.f;
                        float nh = of[j] + y;
                        wf[j] = nh; w2f[j] = nh;
                    }
                    *(float4*)outp = w2;
                } break;
            }
            *(float4*)&C[pos] = w;
        }
    }
}

// ======================= fallback small GEMM (K=3/6, M=32) =======================
#define BMs 64
#define BNs 64
#define BKs 16

__global__ __launch_bounds__(256) void gemm_kernel(GemmP p) {
    __shared__ float As[BKs][BMs+4];
    __shared__ float Bs[BKs][BNs+4];
    int b = blockIdx.z;
    const float* A = p.A + (size_t)b * p.aBS;
    const float* B = p.B + (size_t)b * p.bBS;
    float*       C = p.C + (size_t)b * p.cBS;
    int row0 = blockIdx.y * BMs, col0 = blockIdx.x * BNs;
    int tid = threadIdx.x;
    int tx = tid & 15, ty = tid >> 4;
    float acc[4][4] = {};

    for (int k0 = 0; k0 < p.K; k0 += BKs) {
        if (p.a_cs == 1) {
            #pragma unroll
            for (int i = tid; i < BMs*BKs; i += 256) {
                int m = i >> 4, k = i & 15;
                int gr = row0 + m, gk = k0 + k;
                As[k][m] = (gr < p.M && gk < p.K) ? A[(size_t)gr * p.a_rs + gk] : 0.f;
            }
        } else {
            #pragma unroll
            for (int i = tid; i < BMs*BKs; i += 256) {
                int m = i & 63, k = i >> 6;
                int gr = row0 + m, gk = k0 + k;
                As[k][m] = (gr < p.M && gk < p.K) ?
                    A[(size_t)gr * p.a_rs + (size_t)gk * p.a_cs] : 0.f;
            }
        }
        #pragma unroll
        for (int i = tid; i < BKs*BNs; i += 256) {
            int k = i >> 6, n = i & 63;
            int gk = k0 + k, gc = col0 + n;
            Bs[k][n] = (gk < p.K && gc < p.N) ?
                B[(size_t)gk * p.b_rs + (size_t)gc * p.b_cs] : 0.f;
        }
        __syncthreads();
        #pragma unroll
        for (int k = 0; k < BKs; k++) {
            float4 av = *(const float4*)&As[k][ty*4];
            float4 bv = *(const float4*)&Bs[k][tx*4];
            float a[4] = {av.x, av.y, av.z, av.w};
            float bb[4] = {bv.x, bv.y, bv.z, bv.w};
            #pragma unroll
            for (int i = 0; i < 4; i++)
                #pragma unroll
                for (int j = 0; j < 4; j++)
                    acc[i][j] = fmaf(a[i], bb[j], acc[i][j]);
        }
        __syncthreads();
    }

    #pragma unroll
    for (int i = 0; i < 4; i++) {
        int r = row0 + ty*4 + i;
        if (r >= p.M) break;
        #pragma unroll
        for (int j = 0; j < 4; j++) {
            int c = col0 + tx*4 + j;
            if (c >= p.N) continue;
            float v = acc[i][j];
            size_t pos = (size_t)r * p.ldc + c;
            switch (p.mode) {
                case EP_NONE:
                    C[pos] = v; break;
                case EP_ND: {
                    const float* xx = p.aux + (size_t)b * p.auxBS;
                    C[pos] = 2.f * v - xx[r] - xx[c];
                } break;
                case EP_BN_LRELU: {
                    float y = v * p.s[r] * KBN + p.bias[r];
                    C[pos] = y > 0.f ? y : 0.2f * y;
                } break;
                case EP_VBIAS:
                    C[pos] = v + p.bias[r]; break;
            }
        }
    }
}

// ------------------------- aux kernels -------------------------
__global__ void xx3_kernel(const float* __restrict__ x) {
    int id = blockIdx.x * 256 + threadIdx.x;
    if (id >= BATCH * N2) return;
    const float* p = x + (size_t)id * 3;
    float s = 0.f;
    s = fmaf(p[0], p[0], s); s = fmaf(p[1], p[1], s); s = fmaf(p[2], p[2], s);
    g_xx[id] = s;
}

__global__ void xx64_kernel() {
    int id = blockIdx.x * 256 + threadIdx.x;
    if (id >= BATCH * N2) return;
    const float* p = g_x1t + (size_t)id * 64;
    float s = 0.f;
    #pragma unroll
    for (int i = 0; i < 64; i++) s = fmaf(p[i], p[i], s);
    g_xx[id] = s;
}

// top-40: per-thread max over 8 contiguous elems, then warp0 extract+rescan x40.
// All reductions break ties toward the LOWEST index (matches stable top_k).
__global__ __launch_bounds__(256) void topk_kernel() {
    __shared__ float vals[N2];
    __shared__ float tmax[256];
    __shared__ int   tidx[256];
    int n = blockIdx.x, b = blockIdx.y, t = threadIdx.x;
    const float* row = g_dist + ((size_t)b * N2 + n) * N2;
    for (int i = t; i < N2; i += 256) vals[i] = row[i];
    __syncthreads();
    {
        float m = NEGINF; int a = 0;
        const float4* v4 = (const float4*)&vals[t * 8];
        float4 p0 = v4[0], p1 = v4[1];
        float e[8] = {p0.x, p0.y, p0.z, p0.w, p1.x, p1.y, p1.z, p1.w};
        #pragma unroll
        for (int j = 0; j < 8; j++)
            if (e[j] > m) { m = e[j]; a = t * 8 + j; }
        tmax[t] = m; tidx[t] = a;
    }
    __syncthreads();
    if (t < 32) {
        int* out = g_idx + ((size_t)b * N2 + n) * KNN;
        for (int s = 0; s < KNN; s++) {
            float bm = NEGINF; int bi = 0;
            #pragma unroll
            for (int u = 0; u < 8; u++) {
                float v = tmax[t * 8 + u];
                if (v > bm) { bm = v; bi = t * 8 + u; }
            }
            #pragma unroll
            for (int o = 16; o; o >>= 1) {
                float om = __shfl_xor_sync(0xffffffffu, bm, o);
                int   oi = __shfl_xor_sync(0xffffffffu, bi, o);
                if (om > bm || (om == bm && oi < bi)) { bm = om; bi = oi; }
            }
            int tw = bi;                       // winning thread slot (same on all lanes)
            int widx = tidx[tw];               // its element index (broadcast read)
            if (t == 0) { out[s] = widx; vals[widx] = NEGINF; }
            __syncwarp();
            // rescan owner's 8 elements with lanes 0..7
            float nm = NEGINF; int na = 0x7fffffff;
            if (t < 8) {
                nm = vals[tw * 8 + t];
                na = tw * 8 + t;
            }
            #pragma unroll
            for (int o = 4; o; o >>= 1) {
                float om = __shfl_xor_sync(0xffffffffu, nm, o);
                int   oi = __shfl_xor_sync(0xffffffffu, na, o);
                if (om > nm || (om == nm && oi < na)) { nm = om; na = oi; }
            }
            if (t == 0) { tmax[tw] = nm; tidx[tw] = na; }
            __syncwarp();
        }
    }
}

__global__ void gather1_kernel(const float* __restrict__ x) {
    int nj = blockIdx.x * 256 + threadIdx.x;
    int b = blockIdx.y;
    if (nj >= NJ) return;
    int n = nj / KNN;
    int idx = g_idx[((size_t)b * N2 + n) * KNN + (nj - n * KNN)];
    const float* xn = x + ((size_t)b * N2 + n) * 3;
    const float* xj = x + ((size_t)b * N2 + idx) * 3;
    float* F = g_bufF + (size_t)b * 6 * NJ + nj;
    #pragma unroll
    for (int d = 0; d < 3; d++) {
        F[(size_t)d * NJ]       = xj[d] - xn[d];
        F[(size_t)(3 + d) * NJ] = xn[d];
    }
}

// smem-staged transpose gather: both global sides coalesced
__global__ __launch_bounds__(256) void gather2_kernel() {
    __shared__ float st[32][67];
    __shared__ int sidx[32];
    int b = blockIdx.y;
    int base = blockIdx.x * 32;
    int t = threadIdx.x;
    if (t < 32) {
        int nj = base + t;
        int n = nj / KNN;
        sidx[t] = g_idx[((size_t)b * N2 + n) * KNN + (nj - n * KNN)];
    }
    __syncthreads();
    {
        int pp = t >> 3, l8 = t & 7;
        const float4* src = (const float4*)(g_x1t + ((size_t)b * N2 + sidx[pp]) * 64);
        float4 v0 = src[l8 * 2], v1 = src[l8 * 2 + 1];
        float e[8] = {v0.x, v0.y, v0.z, v0.w, v1.x, v1.y, v1.z, v1.w};
        #pragma unroll
        for (int j = 0; j < 8; j++) st[pp][l8 * 8 + j] = e[j];
    }
    __syncthreads();
    {
        int c = t >> 2, g = t & 3;
        float* G = g_bufA + (size_t)b * 64 * NJ + (size_t)c * NJ + base + g * 8;
        float4 w0, w1;
        float* w0f = (float*)&w0;
        float* w1f = (float*)&w1;
        #pragma unroll
        for (int q = 0; q < 4; q++) w0f[q] = st[g * 8 + q][c];
        #pragma unroll
        for (int q = 0; q < 4; q++) w1f[q] = st[g * 8 + 4 + q][c];
        *(float4*)G = w0;
        *(float4*)(G + 4) = w1;
    }
}

__global__ void maxpool_kernel(const float* __restrict__ E, float* __restrict__ hdst,
                               int write_x1t) {
    int id = blockIdx.x * 256 + threadIdx.x;
    int b = blockIdx.y;
    if (id >= 64 * N2) return;
    int c = id / N2, n = id % N2;
    const float4* e4 = (const float4*)(E + (size_t)b * 64 * NJ + (size_t)c * NJ
                                         + (size_t)n * KNN);
    float4 v = e4[0];
    float m = fmaxf(fmaxf(v.x, v.y), fmaxf(v.z, v.w));
    #pragma unroll
    for (int j = 1; j < 10; j++) {
        v = e4[j];
        m = fmaxf(m, fmaxf(fmaxf(v.x, v.y), fmaxf(v.z, v.w)));
    }
    hdst[(size_t)b * 128 * N2 + (size_t)c * N2 + n] = m;
    if (write_x1t) g_x1t[((size_t)b * N2 + n) * 64 + c] = m;
}

__global__ void w3d_kernel(const float* __restrict__ w3) {
    int id = blockIdx.x * 256 + threadIdx.x;
    if (id >= 64 * 64) return;
    int c = id >> 6, i = id & 63;
    g_w3d[id] = w3[c * 128 + 64 + i] - w3[c * 128 + i];
}

__global__ __launch_bounds__(256) void softmax_kernel() {
    __shared__ float v[N2];
    __shared__ float red[8];
    int n = blockIdx.x, b = blockIdx.y, t = threadIdx.x;
    float* row = g_dist + ((size_t)b * N2 + n) * N2;
    float m = NEGINF;
    for (int i = t; i < N2; i += 256) {
        float x = row[i]; v[i] = x; m = fmaxf(m, x);
    }
    #pragma unroll
    for (int o = 16; o; o >>= 1) m = fmaxf(m, __shfl_xor_sync(0xffffffffu, m, o));
    if ((t & 31) == 0) red[t >> 5] = m;
    __syncthreads();
    float rm = red[0];
    #pragma unroll
    for (int w = 1; w < 8; w++) rm = fmaxf(rm, red[w]);
    __syncthreads();
    float s = 0.f;
    for (int i = t; i < N2; i += 256) {
        float e = __expf(v[i] - rm);
        v[i] = e; s += e;
    }
    #pragma unroll
    for (int o = 16; o; o >>= 1) s += __shfl_xor_sync(0xffffffffu, s, o);
    if ((t & 31) == 0) red[t >> 5] = s;
    __syncthreads();
    float tot = 0.f;
    #pragma unroll
    for (int w = 0; w < 8; w++) tot += red[w];
    float inv = 1.f / tot;
    for (int i = t; i < N2; i += 256) row[i] = v[i] * inv;
}

__global__ void colsum_kernel() {
    int m = blockIdx.x * 256 + threadIdx.x;
    int b = blockIdx.y;
    if (m >= N2) return;
    const float* A = g_dist + (size_t)b * N2 * N2 + m;
    float s = 0.f;
    for (int n = 0; n < N2; n++) s += A[(size_t)n * N2];
    g_cs[b * N2 + m] = 1.f / (1e-9f + s);
}

// combine split-K partials: dd = h - (p0+p1+p2+p3) * cs
__global__ void xr_combine_kernel() {
    const size_t PART = (size_t)BATCH * 128 * N2;
    int id = blockIdx.x * 256 + threadIdx.x;        // float4 index within batch slice
    int b = blockIdx.y;
    size_t base = (size_t)b * 128 * N2 + (size_t)id * 4;
    float4 s0 = *(const float4*)&g_bufA[base];
    float4 s1 = *(const float4*)&g_bufA[base + PART];
    float4 s2 = *(const float4*)&g_bufA[base + 2 * PART];
    float4 s3 = *(const float4*)&g_bufA[base + 3 * PART];
    float4 h4 = *(const float4*)&g_h[base];
    int m0 = (id * 4) & (N2 - 1);
    float4 c4 = *(const float4*)&g_cs[b * N2 + m0];
    float4 w;
    w.x = h4.x - (s0.x + s1.x + s2.x + s3.x) * c4.x;
    w.y = h4.y - (s0.y + s1.y + s2.y + s3.y) * c4.y;
    w.z = h4.z - (s0.z + s1.z + s2.z + s3.z) * c4.z;
    w.w = h4.w - (s0.w + s1.w + s2.w + s3.w) * c4.w;
    *(float4*)&g_dd[base] = w;
}

// ------------------------- host -------------------------
static GemmP make_p(const float* A, const float* B, float* C,
                    int M, int N, int K,
                    int a_rs, int a_cs, int b_rs, int b_cs, int ldc,
                    long long aBS, long long bBS, long long cBS, int mode,
                    const float* s, const float* bias, const float* bias2,
                    const float* aux, long long auxBS, int ldaux,
                    const float* aux2, long long aux2BS,
                    float* aux3, long long aux3BS, int ldaux3,
                    int ksplit, long long kPartStride) {
    GemmP p;
    p.A = A; p.B = B; p.C = C; p.M = M; p.N = N; p.K = K;
    p.a_rs = a_rs; p.a_cs = a_cs; p.b_rs = b_rs; p.b_cs = b_cs; p.ldc = ldc;
    p.aBS = aBS; p.bBS = bBS; p.cBS = cBS; p.mode = mode;
    p.ksplit = ksplit; p.kPartStride = kPartStride;
    p.s = s; p.bias = bias; p.bias2 = bias2;
    p.aux = aux; p.auxBS = auxBS; p.ldaux = ldaux;
    p.aux2 = aux2; p.aux2BS = aux2BS;
    p.aux3 = aux3; p.aux3BS = aux3BS; p.ldaux3 = ldaux3;
    return p;
}

template<int BM, int MAXNCTA>
static void run_big(const float* A, const float* B, float* C,
                    int M, int N, int K,
                    int a_rs, int a_cs, int b_rs, int b_cs, int ldc,
                    long long aBS, long long bBS, long long cBS, int mode,
                    const float* s = nullptr, const float* bias = nullptr,
                    const float* bias2 = nullptr,
                    const float* aux = nullptr, long long auxBS = 0, int ldaux = 0,
                    const float* aux2 = nullptr, long long aux2BS = 0,
                    float* aux3 = nullptr, long long aux3BS = 0, int ldaux3 = 0,
                    int ksplit = 1, long long kPartStride = 0) {
    GemmP p = make_p(A, B, C, M, N, K, a_rs, a_cs, b_rs, b_cs, ldc, aBS, bBS, cBS,
                     mode, s, bias, bias2, aux, auxBS, ldaux, aux2, aux2BS,
                     aux3, aux3BS, ldaux3, ksplit, kPartStride);
    dim3 grid(N / 128, (M / BM) * ksplit, BATCH);
    sgemm2_kernel<BM, MAXNCTA><<<grid, BM * 2>>>(p);
}

static void run_small(const float* A, const float* B, float* C,
                      int M, int N, int K,
                      int a_rs, int a_cs, int b_rs, int b_cs, int ldc,
                      long long aBS, long long bBS, long long cBS, int mode,
                      const float* s = nullptr, const float* bias = nullptr,
                      const float* aux = nullptr, long long auxBS = 0) {
    GemmP p = make_p(A, B, C, M, N, K, a_rs, a_cs, b_rs, b_cs, ldc, aBS, bBS, cBS,
                     mode, s, bias, nullptr, aux, auxBS, 0, nullptr, 0,
                     nullptr, 0, 0, 1, 0);
    dim3 grid((N + BNs - 1) / BNs, (M + BMs - 1) / BMs, BATCH);
    gemm_kernel<<<grid, 256>>>(p);
}

extern "C" void kernel_launch(void* const* d_in, const int* in_sizes, int n_in,
                              void* d_out, int out_size) {
    const float* x      = (const float*)d_in[0];
    const float* w1     = (const float*)d_in[1];
    const float* g1     = (const float*)d_in[2];
    const float* b1     = (const float*)d_in[3];
    const float* w2     = (const float*)d_in[4];
    const float* g2     = (const float*)d_in[5];
    const float* b2     = (const float*)d_in[6];
    const float* w3     = (const float*)d_in[7];
    const float* g3     = (const float*)d_in[8];
    const float* b3     = (const float*)d_in[9];
    const float* w4     = (const float*)d_in[10];
    const float* g4     = (const float*)d_in[11];
    const float* b4     = (const float*)d_in[12];
    // d_in[13..15] = w5/g5/b5: unused by the reference
    const float* sa_qk  = (const float*)d_in[16];
    const float* sa_v   = (const float*)d_in[17];
    const float* sa_vb  = (const float*)d_in[18];
    const float* sa_t   = (const float*)d_in[19];
    const float* sa_tb  = (const float*)d_in[20];
    const float* sa_g   = (const float*)d_in[21];
    const float* sa_b   = (const float*)d_in[22];
    const float* fuse_w = (const float*)d_in[23];
    const float* fuse_g = (const float*)d_in[24];
    const float* fuse_b = (const float*)d_in[25];
    float* out = (float*)d_out;

    float *dist, *bufF, *bufA, *bufB, *h, *xx, *q, *v, *dd, *cs, *tbuf, *outs, *w3d;
    cudaGetSymbolAddress((void**)&dist, g_dist);
    cudaGetSymbolAddress((void**)&bufF, g_bufF);
    cudaGetSymbolAddress((void**)&bufA, g_bufA);
    cudaGetSymbolAddress((void**)&bufB, g_bufB);
    cudaGetSymbolAddress((void**)&h,    g_h);
    cudaGetSymbolAddress((void**)&xx,   g_xx);
    cudaGetSymbolAddress((void**)&q,    g_q);
    cudaGetSymbolAddress((void**)&v,    g_v);
    cudaGetSymbolAddress((void**)&dd,   g_dd);
    cudaGetSymbolAddress((void**)&cs,   g_cs);
    cudaGetSymbolAddress((void**)&tbuf, g_tbuf);
    cudaGetSymbolAddress((void**)&outs, g_outs);
    cudaGetSymbolAddress((void**)&w3d,  g_w3d);

    const long long HB = 128LL * N2;
    const long long DB = (long long)N2 * N2;
    const long long EB = 64LL * NJ;

    // ---------------- stage 1: kNN on coords + edge conv (w1, w2) ----------------
    xx3_kernel<<<(BATCH * N2 + 255) / 256, 256>>>(x);
    run_small(x, x, dist, N2, N2, 3, 3, 1, 1, 3, N2,
              3LL * N2, 3LL * N2, DB, EP_ND, nullptr, nullptr, xx, N2);
    topk_kernel<<<dim3(N2, BATCH), 256>>>();
    gather1_kernel<<<dim3(NJ / 256, BATCH), 256>>>(x);
    run_small(w1, bufF, bufA, 64, NJ, 6, 6, 1, NJ, 1, NJ,
              0, 6LL * NJ, EB, EP_BN_LRELU, g1, b1);
    run_big<64, 4>(w2, bufA, bufB, 64, NJ, 64, 64, 1, NJ, 1, NJ,
                   0, EB, EB, EP_BN_LRELU, g2, b2);
    maxpool_kernel<<<dim3((64 * N2 + 255) / 256, BATCH), 256>>>(bufB, h, 1);
    xx64_kernel<<<(BATCH * N2 + 255) / 256, 256>>>();

    // ---------------- stage 2: kNN on x1 + edge conv (w3, w4) ----------------
    run_big<128, 1>(h, h, dist, N2, N2, 64, 1, N2, N2, 1, N2,
                    HB, HB, DB, EP_ND, nullptr, nullptr, nullptr, xx, N2, 0);
    topk_kernel<<<dim3(N2, BATCH), 256>>>();
    w3d_kernel<<<16, 256>>>(w3);
    run_big<64, 4>(w3d, h, tbuf, 64, N2, 64, 64, 1, N2, 1, N2,
                   0, HB, 64LL * N2, EP_NONE);
    gather2_kernel<<<dim3(NJ / 32, BATCH), 256>>>();
    run_big<64, 4>(w3, bufA, bufB, 64, NJ, 64, 128, 1, NJ, 1, NJ,
                   0, EB, EB, EP_BN_LRELU_T40, g3, b3, nullptr, tbuf, 64LL * N2, N2);
    run_big<64, 4>(w4, bufB, bufA, 64, NJ, 64, 64, 1, NJ, 1, NJ,
                   0, EB, EB, EP_BN_LRELU, g4, b4);
    maxpool_kernel<<<dim3((64 * N2 + 255) / 256, BATCH), 256>>>(bufA, h + 64 * N2, 0);

    // ---------------- 4 self-attention layers ----------------
    for (int l = 0; l < 4; l++) {
        run_small(sa_qk + l * 32 * 128, h, q, 32, N2, 128, 128, 1, N2, 1, N2,
                  0, HB, 32LL * N2, EP_NONE);
        run_big<64, 4>(sa_v + l * 128 * 128, h, v, 128, N2, 128, 128, 1, N2, 1, N2,
                       0, HB, HB, EP_VBIAS, nullptr, sa_vb + l * 128);
        run_big<128, 1>(q, q, dist, N2, N2, 32, 1, N2, N2, 1, N2,
                        32LL * N2, 32LL * N2, DB, EP_NONE);
        softmax_kernel<<<dim3(N2, BATCH), 256>>>();
        colsum_kernel<<<dim3(N2 / 256, BATCH), 256>>>();
        // xr partials: split-K x4 into bufA, then combine -> dd = h - sum*cs
        run_big<128, 1>(v, dist, bufA, 128, N2, N2, N2, 1, N2, 1, N2,
                        HB, DB, HB, EP_NONE,
                        nullptr, nullptr, nullptr, nullptr, 0, 0, nullptr, 0,
                        nullptr, 0, 0, KSPLIT_XR, (long long)BATCH * 128 * N2);
        xr_combine_kernel<<<dim3(128 * N2 / 4 / 256, BATCH), 256>>>();
        run_big<64, 4>(sa_t + l * 128 * 128, dd, h, 128, N2, 128, 128, 1, N2, 1, N2,
                       0, HB, HB, EP_TRES, sa_g + l * 128, sa_tb + l * 128, sa_b + l * 128,
                       nullptr, 0, 0, nullptr, 0,
                       outs + (size_t)l * 128 * N2, 512LL * N2, N2);
    }

    // ---------------- fuse conv ----------------
    run_big<64, 4>(fuse_w, outs, out, 256, N2, 512, 512, 1, N2, 1, N2,
                   0, 512LL * N2, 256LL * N2, EP_BN_LRELU, fuse_g, fuse_b);
}

// round 10
// speedup vs baseline: 1.1068x; 1.1068x over previous
#include <cuda_runtime.h>

#define BATCH 8
#define N2 2048
#define KNN 40
#define NJ (N2*KNN)
#define KBN 0.9999950000374997f
#define NEGINF (-3.402823466e38f)
#define KSPLIT_XR 2

// ------------------------- device scratch (no allocation allowed) -------------------------
__device__ float g_dist[(size_t)BATCH*N2*N2];      // neg-dist / energy / attn (reused)
__device__ int   g_idx[BATCH*N2*KNN];
__device__ float g_bufF[(size_t)BATCH*6*NJ];       // stage-1 gathered features
__device__ float g_bufA[(size_t)BATCH*64*NJ];      // edge-conv ping / xr partials
__device__ float g_bufB[(size_t)BATCH*64*NJ];      // edge-conv pong
__device__ float g_h[BATCH*128*N2];                // [x1;x2] then SA running h (b,c,n)
__device__ float g_x1t[BATCH*N2*64];               // x1 point-major for gathers
__device__ float g_xx[BATCH*N2];
__device__ float g_q[BATCH*32*N2];
__device__ float g_v[BATCH*128*N2];
__device__ float g_dd[BATCH*128*N2];               // d = h - xr
__device__ float g_cs[BATCH*N2];                   // 1/(1e-9+colsum)
__device__ float g_tbuf[BATCH*64*N2];              // hoisted center term
__device__ float g_outs[(size_t)BATCH*512*N2];     // concat of 4 SA outputs
__device__ float g_w3d[64*64];                     // w3b - w3a

enum { EP_NONE=0, EP_ND=1, EP_BN_LRELU=2, EP_BN_LRELU_T40=3, EP_VBIAS=4, EP_XR=5, EP_TRES=6 };

struct GemmP {
    const float* A; const float* B; float* C;
    int M, N, K;
    int a_rs, a_cs;          // A element (m,k) at A[m*a_rs + k*a_cs]
    int b_rs, b_cs;          // B element (k,n) at B[k*b_rs + n*b_cs]
    int ldc;
    long long aBS, bBS, cBS; // per-batch strides (0 = shared weights)
    int mode;
    int ksplit;              // split-K factor (grid.y = (M/BM)*ksplit)
    long long kPartStride;   // C offset per k-chunk
    const float* s; const float* bias; const float* bias2;
    const float* aux;  long long auxBS; int ldaux;   // tbuf / xx / recip
    const float* aux2; long long aux2BS;             // h (for EP_XR)
    float* aux3; long long aux3BS; int ldaux3;       // outs slice (EP_TRES)
};

// ============ fast SGEMM: BMx128 tiles, 8x8 micro, f32x2 FMA, A duplicated in smem ============
// Requirements (guaranteed by callers): K%(16*ksplit)==0, M%BM==0, N%128==0, b_cs==1,
// A either k-contiguous (a_cs==1) or m-contiguous (a_rs==1), 16B-aligned bases.
template<int BM>
__global__ __launch_bounds__(BM*2, (BM==128)?2:4) void sgemm2_kernel(GemmP p) {
    constexpr int THREADS = BM * 2;
    constexpr int NB4 = 512 / THREADS;       // B float4 slots per thread
    constexpr int LDA = 2 * BM;              // duplicated A row (floats)
    __shared__ __align__(16) float As[2][16][LDA];   // element m stored at [2m],[2m+1]
    __shared__ __align__(16) float Bs[2][16][128];

    int b = blockIdx.z;
    const float* A = p.A + (size_t)b * p.aBS;
    const float* B = p.B + (size_t)b * p.bBS;
    int ks   = blockIdx.y % p.ksplit;
    int rowb = blockIdx.y / p.ksplit;
    float* C = p.C + (size_t)b * p.cBS + (size_t)ks * p.kPartStride;
    int kBase = ks * (p.K / p.ksplit);
    int row0 = rowb * BM, col0 = blockIdx.x * 128;
    int tid = threadIdx.x;
    int tx = tid & 15, ty = tid >> 4;

    unsigned long long acc[8][4];
    #pragma unroll
    for (int i = 0; i < 8; i++)
        #pragma unroll
        for (int j = 0; j < 4; j++) acc[i][j] = 0ull;

    float4 ra[2];
    float4 rb[NB4];
    const int T = (p.K / p.ksplit) >> 4;
    const bool akc = (p.a_cs == 1);

    // ---- tile 0 global->reg ----
    {
        if (akc) {
            #pragma unroll
            for (int i = 0; i < 2; i++) {
                int s = tid + i * THREADS;
                int m = s >> 2, k4 = (s & 3) << 2;
                ra[i] = *(const float4*)&A[(size_t)(row0 + m) * p.a_rs + kBase + k4];
            }
        } else {
            #pragma unroll
            for (int i = 0; i < 2; i++) {
                int s = tid + i * THREADS;
                int m4 = s % (BM / 4), k = s / (BM / 4);
                ra[i] = *(const float4*)&A[(size_t)(kBase + k) * p.a_cs + row0 + m4 * 4];
            }
        }
        #pragma unroll
        for (int i = 0; i < NB4; i++) {
            int s = tid + i * THREADS;
            int k = s >> 5, n4 = (s & 31) << 2;
            rb[i] = *(const float4*)&B[(size_t)(kBase + k) * p.b_rs + col0 + n4];
        }
    }
    // ---- reg->smem buf 0 (A duplicated) ----
    {
        if (akc) {
            #pragma unroll
            for (int i = 0; i < 2; i++) {
                int s = tid + i * THREADS;
                int m = s >> 2, k4 = (s & 3) << 2;
                float v[4] = {ra[i].x, ra[i].y, ra[i].z, ra[i].w};
                #pragma unroll
                for (int d = 0; d < 4; d++)
                    *(float2*)&As[0][k4 + d][2 * m] = make_float2(v[d], v[d]);
            }
        } else {
            #pragma unroll
            for (int i = 0; i < 2; i++) {
                int s = tid + i * THREADS;
                int m4 = s % (BM / 4), k = s / (BM / 4);
                float4 lo = make_float4(ra[i].x, ra[i].x, ra[i].y, ra[i].y);
                float4 hi = make_float4(ra[i].z, ra[i].z, ra[i].w, ra[i].w);
                *(float4*)&As[0][k][8 * m4]     = lo;
                *(float4*)&As[0][k][8 * m4 + 4] = hi;
            }
        }
        #pragma unroll
        for (int i = 0; i < NB4; i++) {
            int s = tid + i * THREADS;
            int k = s >> 5, n4 = (s & 31) << 2;
            *(float4*)&Bs[0][k][n4] = rb[i];
        }
    }
    __syncthreads();

    int cur = 0;
    for (int t = 0; t < T; t++) {
        if (t + 1 < T) {
            int k0 = kBase + ((t + 1) << 4);
            if (akc) {
                #pragma unroll
                for (int i = 0; i < 2; i++) {
                    int s = tid + i * THREADS;
                    int m = s >> 2, k4 = (s & 3) << 2;
                    ra[i] = *(const float4*)&A[(size_t)(row0 + m) * p.a_rs + k0 + k4];
                }
            } else {
                #pragma unroll
                for (int i = 0; i < 2; i++) {
                    int s = tid + i * THREADS;
                    int m4 = s % (BM / 4), k = s / (BM / 4);
                    ra[i] = *(const float4*)&A[(size_t)(k0 + k) * p.a_cs + row0 + m4 * 4];
                }
            }
            #pragma unroll
            for (int i = 0; i < NB4; i++) {
                int s = tid + i * THREADS;
                int k = s >> 5, n4 = (s & 31) << 2;
                rb[i] = *(const float4*)&B[(size_t)(k0 + k) * p.b_rs + col0 + n4];
            }
        }
        #pragma unroll
        for (int k = 0; k < 16; k++) {
            const float* ap = &As[cur][k][ty * 16];
            ulonglong2 a01 = *(const ulonglong2*)(ap);
            ulonglong2 a23 = *(const ulonglong2*)(ap + 4);
            ulonglong2 a45 = *(const ulonglong2*)(ap + 8);
            ulonglong2 a67 = *(const ulonglong2*)(ap + 12);
            unsigned long long ad[8] = {a01.x, a01.y, a23.x, a23.y,
                                        a45.x, a45.y, a67.x, a67.y};
            unsigned long long bp[4];
            {
                ulonglong2 q0 = *(const ulonglong2*)&Bs[cur][k][tx * 4];
                ulonglong2 q1 = *(const ulonglong2*)&Bs[cur][k][64 + tx * 4];
                bp[0] = q0.x; bp[1] = q0.y; bp[2] = q1.x; bp[3] = q1.y;
            }
            #pragma unroll
            for (int i = 0; i < 8; i++)
                #pragma unroll
                for (int j = 0; j < 4; j++)
                    asm("fma.rn.f32x2 %0, %1, %2, %0;"
                        : "+l"(acc[i][j]) : "l"(ad[i]), "l"(bp[j]));
        }
        if (t + 1 < T) {
            int nb = cur ^ 1;
            if (akc) {
                #pragma unroll
                for (int i = 0; i < 2; i++) {
                    int s = tid + i * THREADS;
                    int m = s >> 2, k4 = (s & 3) << 2;
                    float v[4] = {ra[i].x, ra[i].y, ra[i].z, ra[i].w};
                    #pragma unroll
                    for (int d = 0; d < 4; d++)
                        *(float2*)&As[nb][k4 + d][2 * m] = make_float2(v[d], v[d]);
                }
            } else {
                #pragma unroll
                for (int i = 0; i < 2; i++) {
                    int s = tid + i * THREADS;
                    int m4 = s % (BM / 4), k = s / (BM / 4);
                    float4 lo = make_float4(ra[i].x, ra[i].x, ra[i].y, ra[i].y);
                    float4 hi = make_float4(ra[i].z, ra[i].z, ra[i].w, ra[i].w);
                    *(float4*)&As[nb][k][8 * m4]     = lo;
                    *(float4*)&As[nb][k][8 * m4 + 4] = hi;
                }
            }
            #pragma unroll
            for (int i = 0; i < NB4; i++) {
                int s = tid + i * THREADS;
                int k = s >> 5, n4 = (s & 31) << 2;
                *(float4*)&Bs[nb][k][n4] = rb[i];
            }
            __syncthreads();
            cur = nb;
        }
    }

    // ---- epilogue: cols col0+tx*4+{0..3} and col0+64+tx*4+{0..3} ----
    #pragma unroll
    for (int i = 0; i < 8; i++) {
        int r = row0 + ty * 8 + i;
        float vals[8];
        #pragma unroll
        for (int j = 0; j < 4; j++) {
            float lo, hi;
            asm("mov.b64 {%0, %1}, %2;" : "=f"(lo), "=f"(hi) : "l"(acc[i][j]));
            vals[2 * j] = lo; vals[2 * j + 1] = hi;
        }
        #pragma unroll
        for (int g = 0; g < 2; g++) {
            int c0 = col0 + g * 64 + tx * 4;
            size_t pos = (size_t)r * p.ldc + c0;
            float4 w;
            float* wf = (float*)&w;
            switch (p.mode) {
                case EP_NONE: {
                    #pragma unroll
                    for (int j = 0; j < 4; j++) wf[j] = vals[g * 4 + j];
                } break;
                case EP_ND: {
                    const float* xx = p.aux + (size_t)b * p.auxBS;
                    float xr = xx[r];
                    float4 xc = *(const float4*)&xx[c0];
                    const float* xcf = (const float*)&xc;
                    #pragma unroll
                    for (int j = 0; j < 4; j++)
                        wf[j] = 2.f * vals[g * 4 + j] - xr - xcf[j];
                } break;
                case EP_BN_LRELU: {
                    float sc = p.s[r] * KBN, bi = p.bias[r];
                    #pragma unroll
                    for (int j = 0; j < 4; j++) {
                        float y = vals[g * 4 + j] * sc + bi;
                        wf[j] = y > 0.f ? y : 0.2f * y;
                    }
                } break;
                case EP_BN_LRELU_T40: {
                    const float* tt = p.aux + (size_t)b * p.auxBS + (size_t)r * p.ldaux;
                    float sc = p.s[r] * KBN, bi = p.bias[r];
                    #pragma unroll
                    for (int j = 0; j < 4; j++) {
                        float y = (vals[g * 4 + j] + tt[(c0 + j) / KNN]) * sc + bi;
                        wf[j] = y > 0.f ? y : 0.2f * y;
                    }
                } break;
                case EP_VBIAS: {
                    float bi = p.bias[r];
                    #pragma unroll
                    for (int j = 0; j < 4; j++) wf[j] = vals[g * 4 + j] + bi;
                } break;
                case EP_XR: {
                    const float* hh = p.aux2 + (size_t)b * p.aux2BS;
                    const float* rc = p.aux  + (size_t)b * p.auxBS;
                    float4 h4 = *(const float4*)&hh[pos];
                    float4 r4 = *(const float4*)&rc[c0];
                    const float* hf = (const float*)&h4;
                    const float* rf = (const float*)&r4;
                    #pragma unroll
                    for (int j = 0; j < 4; j++)
                        wf[j] = hf[j] - vals[g * 4 + j] * rf[j];
                } break;
                case EP_TRES: {
                    float sc = p.s[r] * KBN;
                    float tb = p.bias[r], bb2 = p.bias2[r];
                    float4 o4 = *(const float4*)&C[pos];
                    const float* of = (const float*)&o4;
                    float* outp = p.aux3 + (size_t)b * p.aux3BS + (size_t)r * p.ldaux3 + c0;
                    float4 w2;
                    float* w2f = (float*)&w2;
                    #pragma unroll
                    for (int j = 0; j < 4; j++) {
                        float y = (vals[g * 4 + j] + tb) * sc + bb2;
                        y = y > 0.f ? y : 0.f;
                        float nh = of[j] + y;
                        wf[j] = nh; w2f[j] = nh;
                    }
                    *(float4*)outp = w2;
                } break;
            }
            *(float4*)&C[pos] = w;
        }
    }
}

// ======================= fallback small GEMM (K=3/6, M=32) =======================
#define BMs 64
#define BNs 64
#define BKs 16

__global__ __launch_bounds__(256) void gemm_kernel(GemmP p) {
    __shared__ float As[BKs][BMs+4];
    __shared__ float Bs[BKs][BNs+4];
    int b = blockIdx.z;
    const float* A = p.A + (size_t)b * p.aBS;
    const float* B = p.B + (size_t)b * p.bBS;
    float*       C = p.C + (size_t)b * p.cBS;
    int row0 = blockIdx.y * BMs, col0 = blockIdx.x * BNs;
    int tid = threadIdx.x;
    int tx = tid & 15, ty = tid >> 4;
    float acc[4][4] = {};

    for (int k0 = 0; k0 < p.K; k0 += BKs) {
        if (p.a_cs == 1) {
            #pragma unroll
            for (int i = tid; i < BMs*BKs; i += 256) {
                int m = i >> 4, k = i & 15;
                int gr = row0 + m, gk = k0 + k;
                As[k][m] = (gr < p.M && gk < p.K) ? A[(size_t)gr * p.a_rs + gk] : 0.f;
            }
        } else {
            #pragma unroll
            for (int i = tid; i < BMs*BKs; i += 256) {
                int m = i & 63, k = i >> 6;
                int gr = row0 + m, gk = k0 + k;
                As[k][m] = (gr < p.M && gk < p.K) ?
                    A[(size_t)gr * p.a_rs + (size_t)gk * p.a_cs] : 0.f;
            }
        }
        #pragma unroll
        for (int i = tid; i < BKs*BNs; i += 256) {
            int k = i >> 6, n = i & 63;
            int gk = k0 + k, gc = col0 + n;
            Bs[k][n] = (gk < p.K && gc < p.N) ?
                B[(size_t)gk * p.b_rs + (size_t)gc * p.b_cs] : 0.f;
        }
        __syncthreads();
        #pragma unroll
        for (int k = 0; k < BKs; k++) {
            float4 av = *(const float4*)&As[k][ty*4];
            float4 bv = *(const float4*)&Bs[k][tx*4];
            float a[4] = {av.x, av.y, av.z, av.w};
            float bb[4] = {bv.x, bv.y, bv.z, bv.w};
            #pragma unroll
            for (int i = 0; i < 4; i++)
                #pragma unroll
                for (int j = 0; j < 4; j++)
                    acc[i][j] = fmaf(a[i], bb[j], acc[i][j]);
        }
        __syncthreads();
    }

    #pragma unroll
    for (int i = 0; i < 4; i++) {
        int r = row0 + ty*4 + i;
        if (r >= p.M) break;
        #pragma unroll
        for (int j = 0; j < 4; j++) {
            int c = col0 + tx*4 + j;
            if (c >= p.N) continue;
            float v = acc[i][j];
            size_t pos = (size_t)r * p.ldc + c;
            switch (p.mode) {
                case EP_NONE:
                    C[pos] = v; break;
                case EP_ND: {
                    const float* xx = p.aux + (size_t)b * p.auxBS;
                    C[pos] = 2.f * v - xx[r] - xx[c];
                } break;
                case EP_BN_LRELU: {
                    float y = v * p.s[r] * KBN + p.bias[r];
                    C[pos] = y > 0.f ? y : 0.2f * y;
                } break;
                case EP_VBIAS:
                    C[pos] = v + p.bias[r]; break;
            }
        }
    }
}

// ------------------------- aux kernels -------------------------
__global__ void xx3_kernel(const float* __restrict__ x) {
    int id = blockIdx.x * 256 + threadIdx.x;
    if (id >= BATCH * N2) return;
    const float* p = x + (size_t)id * 3;
    float s = 0.f;
    s = fmaf(p[0], p[0], s); s = fmaf(p[1], p[1], s); s = fmaf(p[2], p[2], s);
    g_xx[id] = s;
}

__global__ void xx64_kernel() {
    int id = blockIdx.x * 256 + threadIdx.x;
    if (id >= BATCH * N2) return;
    const float* p = g_x1t + (size_t)id * 64;
    float s = 0.f;
    #pragma unroll
    for (int i = 0; i < 64; i++) s = fmaf(p[i], p[i], s);
    g_xx[id] = s;
}

// top-40: per-thread max over 8 contiguous elems, then warp0 extract+rescan x40.
// All reductions break ties toward the LOWEST index (matches stable top_k).
__global__ __launch_bounds__(256) void topk_kernel() {
    __shared__ float vals[N2];
    __shared__ float tmax[256];
    __shared__ int   tidx[256];
    int n = blockIdx.x, b = blockIdx.y, t = threadIdx.x;
    const float* row = g_dist + ((size_t)b * N2 + n) * N2;
    for (int i = t; i < N2; i += 256) vals[i] = row[i];
    __syncthreads();
    {
        float m = NEGINF; int a = 0;
        const float4* v4 = (const float4*)&vals[t * 8];
        float4 p0 = v4[0], p1 = v4[1];
        float e[8] = {p0.x, p0.y, p0.z, p0.w, p1.x, p1.y, p1.z, p1.w};
        #pragma unroll
        for (int j = 0; j < 8; j++)
            if (e[j] > m) { m = e[j]; a = t * 8 + j; }
        tmax[t] = m; tidx[t] = a;
    }
    __syncthreads();
    if (t < 32) {
        int* out = g_idx + ((size_t)b * N2 + n) * KNN;
        for (int s = 0; s < KNN; s++) {
            float bm = NEGINF; int bi = 0;
            #pragma unroll
            for (int u = 0; u < 8; u++) {
                float v = tmax[t * 8 + u];
                if (v > bm) { bm = v; bi = t * 8 + u; }
            }
            #pragma unroll
            for (int o = 16; o; o >>= 1) {
                float om = __shfl_xor_sync(0xffffffffu, bm, o);
                int   oi = __shfl_xor_sync(0xffffffffu, bi, o);
                if (om > bm || (om == bm && oi < bi)) { bm = om; bi = oi; }
            }
            int tw = bi;                       // winning thread slot (same on all lanes)
            int widx = tidx[tw];               // its element index (broadcast read)
            if (t == 0) { out[s] = widx; vals[widx] = NEGINF; }
            __syncwarp();
            // rescan owner's 8 elements with lanes 0..7
            float nm = NEGINF; int na = 0x7fffffff;
            if (t < 8) {
                nm = vals[tw * 8 + t];
                na = tw * 8 + t;
            }
            #pragma unroll
            for (int o = 4; o; o >>= 1) {
                float om = __shfl_xor_sync(0xffffffffu, nm, o);
                int   oi = __shfl_xor_sync(0xffffffffu, na, o);
                if (om > nm || (om == nm && oi < na)) { nm = om; na = oi; }
            }
            if (t == 0) { tmax[tw] = nm; tidx[tw] = na; }
            __syncwarp();
        }
    }
}

__global__ void gather1_kernel(const float* __restrict__ x) {
    int nj = blockIdx.x * 256 + threadIdx.x;
    int b = blockIdx.y;
    if (nj >= NJ) return;
    int n = nj / KNN;
    int idx = g_idx[((size_t)b * N2 + n) * KNN + (nj - n * KNN)];
    const float* xn = x + ((size_t)b * N2 + n) * 3;
    const float* xj = x + ((size_t)b * N2 + idx) * 3;
    float* F = g_bufF + (size_t)b * 6 * NJ + nj;
    #pragma unroll
    for (int d = 0; d < 3; d++) {
        F[(size_t)d * NJ]       = xj[d] - xn[d];
        F[(size_t)(3 + d) * NJ] = xn[d];
    }
}

// smem-staged transpose gather: both global sides coalesced
__global__ __launch_bounds__(256) void gather2_kernel() {
    __shared__ float st[32][67];
    __shared__ int sidx[32];
    int b = blockIdx.y;
    int base = blockIdx.x * 32;
    int t = threadIdx.x;
    if (t < 32) {
        int nj = base + t;
        int n = nj / KNN;
        sidx[t] = g_idx[((size_t)b * N2 + n) * KNN + (nj - n * KNN)];
    }
    __syncthreads();
    {
        int pp = t >> 3, l8 = t & 7;
        const float4* src = (const float4*)(g_x1t + ((size_t)b * N2 + sidx[pp]) * 64);
        float4 v0 = src[l8 * 2], v1 = src[l8 * 2 + 1];
        float e[8] = {v0.x, v0.y, v0.z, v0.w, v1.x, v1.y, v1.z, v1.w};
        #pragma unroll
        for (int j = 0; j < 8; j++) st[pp][l8 * 8 + j] = e[j];
    }
    __syncthreads();
    {
        int c = t >> 2, g = t & 3;
        float* G = g_bufA + (size_t)b * 64 * NJ + (size_t)c * NJ + base + g * 8;
        float4 w0, w1;
        float* w0f = (float*)&w0;
        float* w1f = (float*)&w1;
        #pragma unroll
        for (int q = 0; q < 4; q++) w0f[q] = st[g * 8 + q][c];
        #pragma unroll
        for (int q = 0; q < 4; q++) w1f[q] = st[g * 8 + 4 + q][c];
        *(float4*)G = w0;
        *(float4*)(G + 4) = w1;
    }
}

__global__ void maxpool_kernel(const float* __restrict__ E, float* __restrict__ hdst,
                               int write_x1t) {
    int id = blockIdx.x * 256 + threadIdx.x;
    int b = blockIdx.y;
    if (id >= 64 * N2) return;
    int c = id / N2, n = id % N2;
    const float4* e4 = (const float4*)(E + (size_t)b * 64 * NJ + (size_t)c * NJ
                                         + (size_t)n * KNN);
    float4 v = e4[0];
    float m = fmaxf(fmaxf(v.x, v.y), fmaxf(v.z, v.w));
    #pragma unroll
    for (int j = 1; j < 10; j++) {
        v = e4[j];
        m = fmaxf(m, fmaxf(fmaxf(v.x, v.y), fmaxf(v.z, v.w)));
    }
    hdst[(size_t)b * 128 * N2 + (size_t)c * N2 + n] = m;
    if (write_x1t) g_x1t[((size_t)b * N2 + n) * 64 + c] = m;
}

__global__ void w3d_kernel(const float* __restrict__ w3) {
    int id = blockIdx.x * 256 + threadIdx.x;
    if (id >= 64 * 64) return;
    int c = id >> 6, i = id & 63;
    g_w3d[id] = w3[c * 128 + 64 + i] - w3[c * 128 + i];
}

__global__ __launch_bounds__(256) void softmax_kernel() {
    __shared__ float v[N2];
    __shared__ float red[8];
    int n = blockIdx.x, b = blockIdx.y, t = threadIdx.x;
    float* row = g_dist + ((size_t)b * N2 + n) * N2;
    float m = NEGINF;
    for (int i = t; i < N2; i += 256) {
        float x = row[i]; v[i] = x; m = fmaxf(m, x);
    }
    #pragma unroll
    for (int o = 16; o; o >>= 1) m = fmaxf(m, __shfl_xor_sync(0xffffffffu, m, o));
    if ((t & 31) == 0) red[t >> 5] = m;
    __syncthreads();
    float rm = red[0];
    #pragma unroll
    for (int w = 1; w < 8; w++) rm = fmaxf(rm, red[w]);
    __syncthreads();
    float s = 0.f;
    for (int i = t; i < N2; i += 256) {
        float e = __expf(v[i] - rm);
        v[i] = e; s += e;
    }
    #pragma unroll
    for (int o = 16; o; o >>= 1) s += __shfl_xor_sync(0xffffffffu, s, o);
    if ((t & 31) == 0) red[t >> 5] = s;
    __syncthreads();
    float tot = 0.f;
    #pragma unroll
    for (int w = 0; w < 8; w++) tot += red[w];
    float inv = 1.f / tot;
    for (int i = t; i < N2; i += 256) row[i] = v[i] * inv;
}

__global__ void colsum_kernel() {
    int m = blockIdx.x * 256 + threadIdx.x;
    int b = blockIdx.y;
    if (m >= N2) return;
    const float* A = g_dist + (size_t)b * N2 * N2 + m;
    float s = 0.f;
    for (int n = 0; n < N2; n++) s += A[(size_t)n * N2];
    g_cs[b * N2 + m] = 1.f / (1e-9f + s);
}

// combine split-K partials: dd = h - (p0+p1) * cs
__global__ void xr_combine_kernel() {
    const size_t PART = (size_t)BATCH * 128 * N2;
    int id = blockIdx.x * 256 + threadIdx.x;        // float4 index within batch slice
    int b = blockIdx.y;
    size_t base = (size_t)b * 128 * N2 + (size_t)id * 4;
    float4 s0 = *(const float4*)&g_bufA[base];
    float4 s1 = *(const float4*)&g_bufA[base + PART];
    float4 h4 = *(const float4*)&g_h[base];
    int m0 = (id * 4) & (N2 - 1);
    float4 c4 = *(const float4*)&g_cs[b * N2 + m0];
    float4 w;
    w.x = h4.x - (s0.x + s1.x) * c4.x;
    w.y = h4.y - (s0.y + s1.y) * c4.y;
    w.z = h4.z - (s0.z + s1.z) * c4.z;
    w.w = h4.w - (s0.w + s1.w) * c4.w;
    *(float4*)&g_dd[base] = w;
}

// ------------------------- host -------------------------
static GemmP make_p(const float* A, const float* B, float* C,
                    int M, int N, int K,
                    int a_rs, int a_cs, int b_rs, int b_cs, int ldc,
                    long long aBS, long long bBS, long long cBS, int mode,
                    const float* s, const float* bias, const float* bias2,
                    const float* aux, long long auxBS, int ldaux,
                    const float* aux2, long long aux2BS,
                    float* aux3, long long aux3BS, int ldaux3,
                    int ksplit, long long kPartStride) {
    GemmP p;
    p.A = A; p.B = B; p.C = C; p.M = M; p.N = N; p.K = K;
    p.a_rs = a_rs; p.a_cs = a_cs; p.b_rs = b_rs; p.b_cs = b_cs; p.ldc = ldc;
    p.aBS = aBS; p.bBS = bBS; p.cBS = cBS; p.mode = mode;
    p.ksplit = ksplit; p.kPartStride = kPartStride;
    p.s = s; p.bias = bias; p.bias2 = bias2;
    p.aux = aux; p.auxBS = auxBS; p.ldaux = ldaux;
    p.aux2 = aux2; p.aux2BS = aux2BS;
    p.aux3 = aux3; p.aux3BS = aux3BS; p.ldaux3 = ldaux3;
    return p;
}

template<int BM>
static void run_big(const float* A, const float* B, float* C,
                    int M, int N, int K,
                    int a_rs, int a_cs, int b_rs, int b_cs, int ldc,
                    long long aBS, long long bBS, long long cBS, int mode,
                    const float* s = nullptr, const float* bias = nullptr,
                    const float* bias2 = nullptr,
                    const float* aux = nullptr, long long auxBS = 0, int ldaux = 0,
                    const float* aux2 = nullptr, long long aux2BS = 0,
                    float* aux3 = nullptr, long long aux3BS = 0, int ldaux3 = 0,
                    int ksplit = 1, long long kPartStride = 0) {
    GemmP p = make_p(A, B, C, M, N, K, a_rs, a_cs, b_rs, b_cs, ldc, aBS, bBS, cBS,
                     mode, s, bias, bias2, aux, auxBS, ldaux, aux2, aux2BS,
                     aux3, aux3BS, ldaux3, ksplit, kPartStride);
    dim3 grid(N / 128, (M / BM) * ksplit, BATCH);
    sgemm2_kernel<BM><<<grid, BM * 2>>>(p);
}

static void run_small(const float* A, const float* B, float* C,
                      int M, int N, int K,
                      int a_rs, int a_cs, int b_rs, int b_cs, int ldc,
                      long long aBS, long long bBS, long long cBS, int mode,
                      const float* s = nullptr, const float* bias = nullptr,
                      const float* aux = nullptr, long long auxBS = 0) {
    GemmP p = make_p(A, B, C, M, N, K, a_rs, a_cs, b_rs, b_cs, ldc, aBS, bBS, cBS,
                     mode, s, bias, nullptr, aux, auxBS, 0, nullptr, 0,
                     nullptr, 0, 0, 1, 0);
    dim3 grid((N + BNs - 1) / BNs, (M + BMs - 1) / BMs, BATCH);
    gemm_kernel<<<grid, 256>>>(p);
}

extern "C" void kernel_launch(void* const* d_in, const int* in_sizes, int n_in,
                              void* d_out, int out_size) {
    const float* x      = (const float*)d_in[0];
    const float* w1     = (const float*)d_in[1];
    const float* g1     = (const float*)d_in[2];
    const float* b1     = (const float*)d_in[3];
    const float* w2     = (const float*)d_in[4];
    const float* g2     = (const float*)d_in[5];
    const float* b2     = (const float*)d_in[6];
    const float* w3     = (const float*)d_in[7];
    const float* g3     = (const float*)d_in[8];
    const float* b3     = (const float*)d_in[9];
    const float* w4     = (const float*)d_in[10];
    const float* g4     = (const float*)d_in[11];
    const float* b4     = (const float*)d_in[12];
    // d_in[13..15] = w5/g5/b5: unused by the reference
    const float* sa_qk  = (const float*)d_in[16];
    const float* sa_v   = (const float*)d_in[17];
    const float* sa_vb  = (const float*)d_in[18];
    const float* sa_t   = (const float*)d_in[19];
    const float* sa_tb  = (const float*)d_in[20];
    const float* sa_g   = (const float*)d_in[21];
    const float* sa_b   = (const float*)d_in[22];
    const float* fuse_w = (const float*)d_in[23];
    const float* fuse_g = (const float*)d_in[24];
    const float* fuse_b = (const float*)d_in[25];
    float* out = (float*)d_out;

    float *dist, *bufF, *bufA, *bufB, *h, *xx, *q, *v, *dd, *cs, *tbuf, *outs, *w3d;
    cudaGetSymbolAddress((void**)&dist, g_dist);
    cudaGetSymbolAddress((void**)&bufF, g_bufF);
    cudaGetSymbolAddress((void**)&bufA, g_bufA);
    cudaGetSymbolAddress((void**)&bufB, g_bufB);
    cudaGetSymbolAddress((void**)&h,    g_h);
    cudaGetSymbolAddress((void**)&xx,   g_xx);
    cudaGetSymbolAddress((void**)&q,    g_q);
    cudaGetSymbolAddress((void**)&v,    g_v);
    cudaGetSymbolAddress((void**)&dd,   g_dd);
    cudaGetSymbolAddress((void**)&cs,   g_cs);
    cudaGetSymbolAddress((void**)&tbuf, g_tbuf);
    cudaGetSymbolAddress((void**)&outs, g_outs);
    cudaGetSymbolAddress((void**)&w3d,  g_w3d);

    const long long HB = 128LL * N2;
    const long long DB = (long long)N2 * N2;
    const long long EB = 64LL * NJ;

    // ---------------- stage 1: kNN on coords + edge conv (w1, w2) ----------------
    xx3_kernel<<<(BATCH * N2 + 255) / 256, 256>>>(x);
    run_small(x, x, dist, N2, N2, 3, 3, 1, 1, 3, N2,
              3LL * N2, 3LL * N2, DB, EP_ND, nullptr, nullptr, xx, N2);
    topk_kernel<<<dim3(N2, BATCH), 256>>>();
    gather1_kernel<<<dim3(NJ / 256, BATCH), 256>>>(x);
    run_small(w1, bufF, bufA, 64, NJ, 6, 6, 1, NJ, 1, NJ,
              0, 6LL * NJ, EB, EP_BN_LRELU, g1, b1);
    run_big<64>(w2, bufA, bufB, 64, NJ, 64, 64, 1, NJ, 1, NJ,
                0, EB, EB, EP_BN_LRELU, g2, b2);
    maxpool_kernel<<<dim3((64 * N2 + 255) / 256, BATCH), 256>>>(bufB, h, 1);
    xx64_kernel<<<(BATCH * N2 + 255) / 256, 256>>>();

    // ---------------- stage 2: kNN on x1 + edge conv (w3, w4) ----------------
    run_big<128>(h, h, dist, N2, N2, 64, 1, N2, N2, 1, N2,
                 HB, HB, DB, EP_ND, nullptr, nullptr, nullptr, xx, N2, 0);
    topk_kernel<<<dim3(N2, BATCH), 256>>>();
    w3d_kernel<<<16, 256>>>(w3);
    run_big<64>(w3d, h, tbuf, 64, N2, 64, 64, 1, N2, 1, N2,
                0, HB, 64LL * N2, EP_NONE);
    gather2_kernel<<<dim3(NJ / 32, BATCH), 256>>>();
    run_big<64>(w3, bufA, bufB, 64, NJ, 64, 128, 1, NJ, 1, NJ,
                0, EB, EB, EP_BN_LRELU_T40, g3, b3, nullptr, tbuf, 64LL * N2, N2);
    run_big<64>(w4, bufB, bufA, 64, NJ, 64, 64, 1, NJ, 1, NJ,
                0, EB, EB, EP_BN_LRELU, g4, b4);
    maxpool_kernel<<<dim3((64 * N2 + 255) / 256, BATCH), 256>>>(bufA, h + 64 * N2, 0);

    // ---------------- 4 self-attention layers ----------------
    for (int l = 0; l < 4; l++) {
        run_small(sa_qk + l * 32 * 128, h, q, 32, N2, 128, 128, 1, N2, 1, N2,
                  0, HB, 32LL * N2, EP_NONE);
        run_big<64>(sa_v + l * 128 * 128, h, v, 128, N2, 128, 128, 1, N2, 1, N2,
                    0, HB, HB, EP_VBIAS, nullptr, sa_vb + l * 128);
        run_big<128>(q, q, dist, N2, N2, 32, 1, N2, N2, 1, N2,
                     32LL * N2, 32LL * N2, DB, EP_NONE);
        softmax_kernel<<<dim3(N2, BATCH), 256>>>();
        colsum_kernel<<<dim3(N2 / 256, BATCH), 256>>>();
        // xr partials: split-K x2 into bufA, then combine -> dd = h - sum*cs
        run_big<128>(v, dist, bufA, 128, N2, N2, N2, 1, N2, 1, N2,
                     HB, DB, HB, EP_NONE,
                     nullptr, nullptr, nullptr, nullptr, 0, 0, nullptr, 0,
                     nullptr, 0, 0, KSPLIT_XR, (long long)BATCH * 128 * N2);
        xr_combine_kernel<<<dim3(128 * N2 / 4 / 256, BATCH), 256>>>();
        run_big<64>(sa_t + l * 128 * 128, dd, h, 128, N2, 128, 128, 1, N2, 1, N2,
                    0, HB, HB, EP_TRES, sa_g + l * 128, sa_tb + l * 128, sa_b + l * 128,
                    nullptr, 0, 0, nullptr, 0,
                    outs + (size_t)l * 128 * N2, 512LL * N2, N2);
    }

    // ---------------- fuse conv ----------------
    run_big<128>(fuse_w, outs, out, 256, N2, 512, 512, 1, N2, 1, N2,
                 0, 512LL * N2, 256LL * N2, EP_BN_LRELU, fuse_g, fuse_b);
}